// round 6
// baseline (speedup 1.0000x reference)
#include <cuda_runtime.h>

#define CROP 512
#define GRID_N 8
#define NBINS 256
#define TILE 64        // CROP / GRID_N
#define SRC_W 640
#define SRC_H 640
#define NB 64          // batch
#define NWARP 8        // warps per hist block

// LUT scratch: 64 batches * 8*8 tiles * 256 bins * 4B = 4 MB
// Stored PRE-DIVIDED by 255 (so apply kernel skips the final divide).
__device__ float g_luts[NB * GRID_N * GRID_N * NBINS];

// ---------------------------------------------------------------------------
// Kernel 1: one block per (batch, tile).
//   clahe batch  -> histogram -> clip -> redistribute -> cumsum -> LUT
//                   (reads use the mirror identity: a flipped tile's pixel SET
//                    is an ascending contiguous range, so loads are coalesced
//                    ascending regardless of flips)
//   copy batch   -> copy its 64x64 output tile (flip-ordered), overlapping
//                   DRAM traffic with the clahe blocks' atomic work.
// ---------------------------------------------------------------------------
__global__ void clahe_hist_or_copy_kernel(const float* __restrict__ x,
                                          const int* __restrict__ hflip,
                                          const int* __restrict__ vflip,
                                          const int* __restrict__ offy,
                                          const int* __restrict__ offx,
                                          const int* __restrict__ apply_clahe,
                                          float* __restrict__ out) {
    const int b    = blockIdx.x >> 6;     // 64 tiles per batch
    const int tile = blockIdx.x & 63;
    const int ty   = tile >> 3;
    const int tx   = tile & 7;
    const int t    = threadIdx.x;         // 0..255

    const int   hf = hflip[b];
    const int   vf = vflip[b];
    const int   oy = offy[b];
    const int   ox = offx[b];
    const float* xb = x + (size_t)b * (SRC_W * SRC_H);

    if (apply_clahe[b]) {
        // ---------------- histogram path ----------------
        const int w    = t >> 5;
        const int lane = t & 31;

        __shared__ int   hist[NWARP][NBINS];
        __shared__ float wsum[NWARP];

        #pragma unroll
        for (int k = 0; k < NWARP; k++) hist[k][t] = 0;
        __syncthreads();

        // mirror identity: ascending contiguous source range
        const int rstart = vf ? (SRC_H - oy - ty * TILE - TILE) : (oy + ty * TILE);
        const int cstart = hf ? (SRC_W - ox - tx * TILE - TILE) : (ox + tx * TILE);
        const float* p = xb + (rstart + (t >> 6)) * SRC_W + cstart + (t & 63);

        #pragma unroll
        for (int k = 0; k < 16; k++) {
            float v = __ldg(p + k * 4 * SRC_W);
            int bin = (int)(v * (float)NBINS);      // v in [0,1) -> 0..255
            atomicAdd(&hist[w][bin], 1);
        }
        __syncthreads();

        // fold per-warp histograms; clip_val = 0.8 * 4096 / 256 = 12.8
        int hsum = 0;
        #pragma unroll
        for (int k = 0; k < NWARP; k++) hsum += hist[k][t];

        float clipped = fminf((float)hsum, 12.8f);

        // inclusive scan of `clipped` over 256 threads (shuffle + 2 barriers)
        float v = clipped;
        #pragma unroll
        for (int s = 1; s < 32; s <<= 1) {
            float n = __shfl_up_sync(0xffffffffu, v, s);
            if (lane >= s) v += n;
        }
        if (lane == 31) wsum[w] = v;
        __syncthreads();
        if (w == 0 && lane < NWARP) {
            float ws = wsum[lane];
            #pragma unroll
            for (int s = 1; s < NWARP; s <<= 1) {
                float n = __shfl_up_sync(0xffu, ws, s);
                if (lane >= s) ws += n;
            }
            wsum[lane] = ws;
        }
        __syncthreads();

        float cum = v + ((w > 0) ? wsum[w - 1] : 0.0f);
        float total_clipped = wsum[NWARP - 1];
        float excess = 4096.0f - total_clipped;

        // lut = clip(cumsum(clipped + excess/256) / 4096, 0, 1)
        float lut = (cum + excess * (float)(t + 1) * (1.0f / 256.0f)) * (1.0f / 4096.0f);
        lut = fminf(fmaxf(lut, 0.0f), 1.0f);

        g_luts[(((b * GRID_N + ty) * GRID_N + tx) << 8) + t] = lut;
    } else {
        // ---------------- copy path (flip order matters) ----------------
        const int j  = t & 63;            // tile-local column
        const int i0 = t >> 6;            // tile-local row 0..3

        const int rs      = vf ? -SRC_W : SRC_W;
        const int rowbase = vf ? (SRC_H - 1 - oy) : oy;
        const int gj      = tx * TILE + j;
        const int sw      = hf ? (SRC_W - 1 - ox - gj) : (ox + gj);
        const int gi0     = ty * TILE + i0;

        const float* p = xb + rowbase * SRC_W + sw + gi0 * rs;
        float*       q = out + ((size_t)b << 18) + (gi0 << 9) + gj;
        const int pstep = 4 * rs;
        const int qstep = 4 << 9;

        #pragma unroll
        for (int k = 0; k < 16; k++) {
            __stcs(q, __ldg(p));
            p += pstep; q += qstep;
        }
    }
}

// ---------------------------------------------------------------------------
// Kernel 2: clahe batches only. One block per (batch, interpolation-cell);
// each thread owns one column (1-wavefront LDG/STG), 4 rows/iter; flips via
// signed strides; fy/pointers strength-reduced. Reads mostly hit L2 (warmed
// by kernel 1's histogram pass).
// ---------------------------------------------------------------------------
__global__ void __launch_bounds__(256, 7)
clahe_apply_kernel(const float* __restrict__ x,
                   const int* __restrict__ hflip,
                   const int* __restrict__ vflip,
                   const int* __restrict__ offy,
                   const int* __restrict__ offx,
                   const int* __restrict__ apply_clahe,
                   float* __restrict__ out) {
    const int b = blockIdx.y;
    if (!apply_clahe[b]) return;          // handled by kernel 1

    const int cell = blockIdx.x;          // 0..80
    const int cy   = cell / 9;
    const int cx   = cell - cy * 9;
    const int t    = threadIdx.x;

    const int ystart = (cy == 0) ? 0 : cy * TILE - 32;
    const int yend   = (cy == 8) ? CROP : cy * TILE + 32;
    const int xstart = (cx == 0) ? 0 : cx * TILE - 32;
    const int xend   = (cx == 8) ? CROP : cx * TILE + 32;
    const int xsize  = xend - xstart;               // 32 or 64
    const int ysize  = yend - ystart;               // 32 or 64
    const int xshift = (xsize == 64) ? 6 : 5;
    const int nrg    = 256 >> xshift;               // 4 or 8
    const int stride = nrg * 4;

    __shared__ float4 slut[NBINS];
    {
        const int y0 = min(max(cy - 1, 0), GRID_N - 1);
        const int y1 = min(cy, GRID_N - 1);
        const int x0 = min(max(cx - 1, 0), GRID_N - 1);
        const int x1 = min(cx, GRID_N - 1);
        const float* lb = g_luts + ((size_t)b << 14);
        const float* p00 = lb + ((y0 * GRID_N + x0) << 8);
        const float* p01 = lb + ((y0 * GRID_N + x1) << 8);
        const float* p10 = lb + ((y1 * GRID_N + x0) << 8);
        const float* p11 = lb + ((y1 * GRID_N + x1) << 8);
        slut[t] = make_float4(p00[t], p01[t], p10[t], p11[t]);
        __syncthreads();
    }

    const int   hf = hflip[b];
    const int   vf = vflip[b];
    const int   oy = offy[b];
    const int   ox = offx[b];
    const float* xb = x + (size_t)b * (SRC_W * SRC_H);
    float*       ob = out + ((size_t)b << 18);

    const int tcol = t & (xsize - 1);
    const int trow = t >> xshift;
    const int gj   = xstart + tcol;
    const int gi0  = ystart + trow;

    const int rs = vf ? -SRC_W : SRC_W;
    const int sw = hf ? (SRC_W - 1 - ox - gj) : (ox + gj);
    const int rowbase = vf ? (SRC_H - 1 - oy) : oy;
    const float* p = xb + rowbase * SRC_W + sw + gi0 * rs;
    const int o1 = nrg * rs, o2 = 2 * nrg * rs, o3 = 3 * nrg * rs;
    const int pstep = stride * rs;

    float* q = ob + (gi0 << 9) + gj;
    const int qo = nrg << 9;
    const int qstep = stride << 9;

    const int niter = ysize / stride;     // 1, 2 or 4

    const float ybase = 0.5f * (1.0f / TILE) - 0.5f - (float)(cy - 1);
    const float xbase = 0.5f * (1.0f / TILE) - 0.5f - (float)(cx - 1);
    const float fx  = fmaf((float)gj, 1.0f / TILE, xbase);
    float       fy  = fmaf((float)gi0, 1.0f / TILE, ybase);
    const float dfy = (float)nrg * (1.0f / TILE);       // exact dyadic
    const float sfy = (float)stride * (1.0f / TILE);    // exact dyadic

    for (int it = 0; it < niter; it++) {
        float v0 = __ldg(p);
        float v1 = __ldg(p + o1);
        float v2 = __ldg(p + o2);
        float v3 = __ldg(p + o3);

        int b0 = (int)(v0 * (float)NBINS);
        int b1 = (int)(v1 * (float)NBINS);
        int b2 = (int)(v2 * (float)NBINS);
        int b3 = (int)(v3 * (float)NBINS);

        float4 q0 = slut[b0];
        float4 q1 = slut[b1];
        float4 q2 = slut[b2];
        float4 q3 = slut[b3];

        float fy0 = fy;
        float fy1 = fy + dfy;
        float fy2 = fy + 2.0f * dfy;
        float fy3 = fy + 3.0f * dfy;

        float t0  = fmaf(fx, q0.y - q0.x, q0.x);
        float b0f = fmaf(fx, q0.w - q0.z, q0.z);
        float t1  = fmaf(fx, q1.y - q1.x, q1.x);
        float b1f = fmaf(fx, q1.w - q1.z, q1.z);
        float t2  = fmaf(fx, q2.y - q2.x, q2.x);
        float b2f = fmaf(fx, q2.w - q2.z, q2.z);
        float t3  = fmaf(fx, q3.y - q3.x, q3.x);
        float b3f = fmaf(fx, q3.w - q3.z, q3.z);

        __stcs(q,          fmaf(fy0, b0f - t0, t0));
        __stcs(q + qo,     fmaf(fy1, b1f - t1, t1));
        __stcs(q + 2 * qo, fmaf(fy2, b2f - t2, t2));
        __stcs(q + 3 * qo, fmaf(fy3, b3f - t3, t3));

        p += pstep; q += qstep; fy += sfy;
    }
}

extern "C" void kernel_launch(void* const* d_in, const int* in_sizes, int n_in,
                              void* d_out, int out_size) {
    const float* x          = (const float*)d_in[0];
    const int*   hflip      = (const int*)d_in[1];
    const int*   vflip      = (const int*)d_in[2];
    const int*   offy       = (const int*)d_in[3];
    const int*   offx       = (const int*)d_in[4];
    const int*   apply_clahe= (const int*)d_in[5];
    float*       out        = (float*)d_out;

    // Kernel 1: hist (clahe batches) or tile copy (non-clahe batches)
    clahe_hist_or_copy_kernel<<<NB * GRID_N * GRID_N, NBINS>>>(
        x, hflip, vflip, offy, offx, apply_clahe, out);

    // Kernel 2: clahe batches only
    dim3 grid2(9 * 9, NB);
    clahe_apply_kernel<<<grid2, 256>>>(
        x, hflip, vflip, offy, offx, apply_clahe, out);
}

// round 7
// speedup vs baseline: 1.0095x; 1.0095x over previous
#include <cuda_runtime.h>

#define CROP 512
#define GRID_N 8
#define NBINS 256
#define TILE 64        // CROP / GRID_N
#define SRC_W 640
#define SRC_H 640
#define NB 64          // batch
#define NWARP 8        // warps per block

// LUT scratch (values pre-divided by 255): 64 * 64 tiles * 256 bins * 4B = 4 MB
__device__ float g_luts[NB * GRID_N * GRID_N * NBINS];
// per-batch "LUTs ready" counters
__device__ int g_cnt[NB];

__global__ void reset_cnt_kernel() {
    g_cnt[threadIdx.x] = 0;
}

__device__ __forceinline__ float ldcg_f(const float* p) {
    float v;
    asm volatile("ld.global.cg.f32 %0, [%1];" : "=f"(v) : "l"(p));
    return v;
}

// ---------------------------------------------------------------------------
// Fused kernel: one block per (batch, tile).
//  copy batch : stream the 64x64 output tile (flip-ordered), no sync.
//  clahe batch: read tile in OUTPUT order, histogram + retain packed bins in
//               registers -> clip/redistribute/scan -> publish LUT ->
//               inter-block batch barrier -> stage 4 quadrant float4 tables
//               in smem -> apply from retained bins (NO input re-read).
// ---------------------------------------------------------------------------
__global__ void __launch_bounds__(256)
clahe_fused_kernel(const float* __restrict__ x,
                   const int* __restrict__ hflip,
                   const int* __restrict__ vflip,
                   const int* __restrict__ offy,
                   const int* __restrict__ offx,
                   const int* __restrict__ apply_clahe,
                   float* __restrict__ out) {
    const int b    = blockIdx.x >> 6;
    const int tile = blockIdx.x & 63;
    const int ty   = tile >> 3;
    const int tx   = tile & 7;
    const int t    = threadIdx.x;         // 0..255

    const int   hf = hflip[b];
    const int   vf = vflip[b];
    const int   oy = offy[b];
    const int   ox = offx[b];
    const float* xb = x + (size_t)b * (SRC_W * SRC_H);

    // per-thread output-tile mapping: column j, rows i0+4k (k=0..15)
    const int j   = t & 63;
    const int i0  = t >> 6;
    const int gj  = tx * TILE + j;
    const int gi0 = ty * TILE + i0;

    // flip-folded source addressing
    const int rs      = vf ? -SRC_W : SRC_W;
    const int rowbase = vf ? (SRC_H - 1 - oy) : oy;
    const int sw      = hf ? (SRC_W - 1 - ox - gj) : (ox + gj);
    const float* p    = xb + rowbase * SRC_W + sw + gi0 * rs;
    const int pstep   = 4 * rs;

    float* q0 = out + ((size_t)b << 18) + (gi0 << 9) + gj;
    const int qstep = 4 << 9;

    if (!apply_clahe[b]) {
        // ---------------- copy path ----------------
        float* q = q0;
        #pragma unroll
        for (int k = 0; k < 16; k++) {
            __stcs(q, __ldg(p));
            p += pstep; q += qstep;
        }
        return;
    }

    // ---------------- clahe path ----------------
    __shared__ __align__(16) unsigned char smem_raw[4 * NBINS * 16];  // 16 KB
    __shared__ float wsum[NWARP];

    int (*hist)[NBINS] = (int (*)[NBINS])smem_raw;
    const int w    = t >> 5;
    const int lane = t & 31;

    #pragma unroll
    for (int k = 0; k < NWARP; k++) hist[k][t] = 0;
    __syncthreads();

    // read (output order), histogram, retain bins packed as bytes
    unsigned int packed[4] = {0u, 0u, 0u, 0u};
    #pragma unroll
    for (int k = 0; k < 16; k++) {
        float v = __ldg(p);
        p += pstep;
        int bin = (int)(v * (float)NBINS);          // v in [0,1) -> 0..255
        atomicAdd(&hist[w][bin], 1);
        packed[k >> 2] |= (unsigned int)bin << ((k & 3) * 8);
    }
    __syncthreads();

    // fold per-warp histograms; clip at 0.8*4096/256 = 12.8
    int hsum = 0;
    #pragma unroll
    for (int k = 0; k < NWARP; k++) hsum += hist[k][t];
    float clipped = fminf((float)hsum, 12.8f);

    // inclusive 256-thread scan (shuffle + 2 barriers)
    float v = clipped;
    #pragma unroll
    for (int s = 1; s < 32; s <<= 1) {
        float n = __shfl_up_sync(0xffffffffu, v, s);
        if (lane >= s) v += n;
    }
    if (lane == 31) wsum[w] = v;
    __syncthreads();
    if (w == 0 && lane < NWARP) {
        float ws = wsum[lane];
        #pragma unroll
        for (int s = 1; s < NWARP; s <<= 1) {
            float n = __shfl_up_sync(0xffu, ws, s);
            if (lane >= s) ws += n;
        }
        wsum[lane] = ws;
    }
    __syncthreads();

    float cum    = v + ((w > 0) ? wsum[w - 1] : 0.0f);
    float excess = 4096.0f - wsum[NWARP - 1];

    // lut = clip(cumsum(clipped + excess/256)/4096, 0, 1)
    float lut = (cum + excess * (float)(t + 1) * (1.0f / 256.0f)) * (1.0f / 4096.0f);
    lut = fminf(fmaxf(lut, 0.0f), 1.0f);
    g_luts[(((b * GRID_N + ty) * GRID_N + tx) << 8) + t] = lut;

    // publish: all stores visible, then count this tile
    __threadfence();
    __syncthreads();
    if (t == 0) {
        atomicAdd(&g_cnt[b], 1);
        // spin until all 64 tiles of this batch have published
        volatile int* vc = &g_cnt[b];
        while (*vc < 64) { }
        __threadfence();
    }
    __syncthreads();

    // stage 4 quadrant tables (overwrites hist region)
    float4* T = (float4*)smem_raw;        // T[q*256 + bin]
    {
        const int ya0 = max(ty - 1, 0), ya1 = ty;
        const int yb0 = ty,             yb1 = min(ty + 1, GRID_N - 1);
        const int xa0 = max(tx - 1, 0), xa1 = tx;
        const int xb0 = tx,             xb1 = min(tx + 1, GRID_N - 1);
        const float* lb = g_luts + ((size_t)b << 14);
        #define LUTQ(yy, xx) ldcg_f(lb + (((yy) * GRID_N + (xx)) << 8) + t)
        T[0 * NBINS + t] = make_float4(LUTQ(ya0, xa0), LUTQ(ya0, xa1), LUTQ(ya1, xa0), LUTQ(ya1, xa1));
        T[1 * NBINS + t] = make_float4(LUTQ(ya0, xb0), LUTQ(ya0, xb1), LUTQ(ya1, xb0), LUTQ(ya1, xb1));
        T[2 * NBINS + t] = make_float4(LUTQ(yb0, xa0), LUTQ(yb0, xa1), LUTQ(yb1, xa0), LUTQ(yb1, xa1));
        T[3 * NBINS + t] = make_float4(LUTQ(yb0, xb0), LUTQ(yb0, xb1), LUTQ(yb1, xb0), LUTQ(yb1, xb1));
        #undef LUTQ
    }
    __syncthreads();

    // apply from retained bins (no input re-read)
    const int qx = j >> 5;
    const float fx = (qx ? ((float)j - 31.5f) : ((float)j + 32.5f)) * (1.0f / TILE);

    const float4* Ta = T + qx * NBINS;          // rows i < 32 (qy=0)
    const float4* Tb = T + (2 + qx) * NBINS;    // rows i >= 32 (qy=1)

    float* q = q0;
    float fy = ((float)i0 + 32.5f) * (1.0f / TILE);   // exact dyadic
    #pragma unroll
    for (int k = 0; k < 8; k++) {
        int bin = (packed[k >> 2] >> ((k & 3) * 8)) & 255;
        float4 tt = Ta[bin];
        float top = fmaf(fx, tt.y - tt.x, tt.x);
        float bot = fmaf(fx, tt.w - tt.z, tt.z);
        __stcs(q, fmaf(fy, bot - top, top));
        q += qstep; fy += (4.0f / TILE);
    }
    fy = ((float)i0 + 0.5f) * (1.0f / TILE);
    #pragma unroll
    for (int k = 8; k < 16; k++) {
        int bin = (packed[k >> 2] >> ((k & 3) * 8)) & 255;
        float4 tt = Tb[bin];
        float top = fmaf(fx, tt.y - tt.x, tt.x);
        float bot = fmaf(fx, tt.w - tt.z, tt.z);
        __stcs(q, fmaf(fy, bot - top, top));
        q += qstep; fy += (4.0f / TILE);
    }
}

extern "C" void kernel_launch(void* const* d_in, const int* in_sizes, int n_in,
                              void* d_out, int out_size) {
    const float* x          = (const float*)d_in[0];
    const int*   hflip      = (const int*)d_in[1];
    const int*   vflip      = (const int*)d_in[2];
    const int*   offy       = (const int*)d_in[3];
    const int*   offx       = (const int*)d_in[4];
    const int*   apply_clahe= (const int*)d_in[5];
    float*       out        = (float*)d_out;

    reset_cnt_kernel<<<1, NB>>>();
    clahe_fused_kernel<<<NB * GRID_N * GRID_N, NBINS>>>(
        x, hflip, vflip, offy, offx, apply_clahe, out);
}

// round 8
// speedup vs baseline: 1.0598x; 1.0498x over previous
#include <cuda_runtime.h>

#define CROP 512
#define GRID_N 8
#define NBINS 256
#define TILE 64        // CROP / GRID_N
#define SRC_W 640
#define SRC_H 640
#define NB 64          // batch
#define NWARP 8        // warps per block

// LUT scratch (values pre-divided by 255): 64 * 64 tiles * 256 bins * 4B = 4 MB
__device__ float g_luts[NB * GRID_N * GRID_N * NBINS];
// monotonic arrival / generation counters (NEVER reset; replay-safe)
__device__ unsigned g_cnt[NB];
__device__ unsigned g_gen[NB];

__device__ __forceinline__ float ldcg_f(const float* p) {
    float v;
    asm volatile("ld.global.cg.f32 %0, [%1];" : "=f"(v) : "l"(p));
    return v;
}

// ---------------------------------------------------------------------------
// Fused kernel: one block per (batch, tile).
//  copy batch : stream the 64x64 output tile (flip-ordered), no sync.
//  clahe batch: read tile in OUTPUT order, histogram + retain packed bins in
//               registers -> clip/redistribute/scan -> publish LUT ->
//               generation-counter batch barrier (no reset kernel needed) ->
//               stage 4 quadrant float4 tables in smem -> apply from retained
//               bins (NO input re-read).
// ---------------------------------------------------------------------------
__global__ void __launch_bounds__(256)
clahe_fused_kernel(const float* __restrict__ x,
                   const int* __restrict__ hflip,
                   const int* __restrict__ vflip,
                   const int* __restrict__ offy,
                   const int* __restrict__ offx,
                   const int* __restrict__ apply_clahe,
                   float* __restrict__ out) {
    const int b    = blockIdx.x >> 6;
    const int tile = blockIdx.x & 63;
    const int ty   = tile >> 3;
    const int tx   = tile & 7;
    const int t    = threadIdx.x;         // 0..255

    const int   hf = hflip[b];
    const int   vf = vflip[b];
    const int   oy = offy[b];
    const int   ox = offx[b];
    const float* xb = x + (size_t)b * (SRC_W * SRC_H);

    // per-thread output-tile mapping: column j, rows i0+4k (k=0..15)
    const int j   = t & 63;
    const int i0  = t >> 6;
    const int gj  = tx * TILE + j;
    const int gi0 = ty * TILE + i0;

    // flip-folded source addressing
    const int rs      = vf ? -SRC_W : SRC_W;
    const int rowbase = vf ? (SRC_H - 1 - oy) : oy;
    const int sw      = hf ? (SRC_W - 1 - ox - gj) : (ox + gj);
    const float* p    = xb + rowbase * SRC_W + sw + gi0 * rs;
    const int pstep   = 4 * rs;

    float* q0 = out + ((size_t)b << 18) + (gi0 << 9) + gj;
    const int qstep = 4 << 9;

    if (!apply_clahe[b]) {
        // ---------------- copy path ----------------
        float* q = q0;
        #pragma unroll
        for (int k = 0; k < 16; k++) {
            __stcs(q, __ldg(p));
            p += pstep; q += qstep;
        }
        return;
    }

    // ---------------- clahe path ----------------
    __shared__ __align__(16) unsigned char smem_raw[4 * NBINS * 16];  // 16 KB
    __shared__ float wsum[NWARP];

    int (*hist)[NBINS] = (int (*)[NBINS])smem_raw;
    const int w    = t >> 5;
    const int lane = t & 31;

    #pragma unroll
    for (int k = 0; k < NWARP; k++) hist[k][t] = 0;
    __syncthreads();

    // read (output order), histogram, retain bins packed as bytes
    unsigned int packed[4] = {0u, 0u, 0u, 0u};
    #pragma unroll
    for (int k = 0; k < 16; k++) {
        float v = __ldg(p);
        p += pstep;
        int bin = (int)(v * (float)NBINS);          // v in [0,1) -> 0..255
        atomicAdd(&hist[w][bin], 1);
        packed[k >> 2] |= (unsigned int)bin << ((k & 3) * 8);
    }
    __syncthreads();

    // fold per-warp histograms; clip at 0.8*4096/256 = 12.8
    int hsum = 0;
    #pragma unroll
    for (int k = 0; k < NWARP; k++) hsum += hist[k][t];
    float clipped = fminf((float)hsum, 12.8f);

    // inclusive 256-thread scan (shuffle + 2 barriers)
    float v = clipped;
    #pragma unroll
    for (int s = 1; s < 32; s <<= 1) {
        float n = __shfl_up_sync(0xffffffffu, v, s);
        if (lane >= s) v += n;
    }
    if (lane == 31) wsum[w] = v;
    __syncthreads();
    if (w == 0 && lane < NWARP) {
        float ws = wsum[lane];
        #pragma unroll
        for (int s = 1; s < NWARP; s <<= 1) {
            float n = __shfl_up_sync(0xffu, ws, s);
            if (lane >= s) ws += n;
        }
        wsum[lane] = ws;
    }
    __syncthreads();

    float cum    = v + ((w > 0) ? wsum[w - 1] : 0.0f);
    float excess = 4096.0f - wsum[NWARP - 1];

    // lut = clip(cumsum(clipped + excess/256)/4096, 0, 1)
    float lut = (cum + excess * (float)(t + 1) * (1.0f / 256.0f)) * (1.0f / 4096.0f);
    lut = fminf(fmaxf(lut, 0.0f), 1.0f);
    g_luts[(((b * GRID_N + ty) * GRID_N + tx) << 8) + t] = lut;

    // ---- generation-counter batch barrier (monotonic, replay-safe) ----
    __syncthreads();                       // all LUT stores issued block-wide
    if (t == 0) {
        __threadfence();                   // publish this block's LUT stores
        unsigned my = atomicAdd(&g_cnt[b], 1u);
        unsigned target = (my >> 6) + 1u;  // this replay's cohort generation
        if ((my & 63u) == 63u)
            atomicAdd(&g_gen[b], 1u);      // 64th arriver releases the cohort
        while (*(volatile unsigned*)&g_gen[b] < target)
            __nanosleep(64);
        __threadfence();                   // acquire peers' LUT stores
    }
    __syncthreads();

    // stage 4 quadrant tables (overwrites hist region)
    float4* T = (float4*)smem_raw;        // T[q*256 + bin]
    {
        const int ya0 = max(ty - 1, 0), ya1 = ty;
        const int yb0 = ty,             yb1 = min(ty + 1, GRID_N - 1);
        const int xa0 = max(tx - 1, 0), xa1 = tx;
        const int xb0 = tx,             xb1 = min(tx + 1, GRID_N - 1);
        const float* lb = g_luts + ((size_t)b << 14);
        #define LUTQ(yy, xx) ldcg_f(lb + (((yy) * GRID_N + (xx)) << 8) + t)
        T[0 * NBINS + t] = make_float4(LUTQ(ya0, xa0), LUTQ(ya0, xa1), LUTQ(ya1, xa0), LUTQ(ya1, xa1));
        T[1 * NBINS + t] = make_float4(LUTQ(ya0, xb0), LUTQ(ya0, xb1), LUTQ(ya1, xb0), LUTQ(ya1, xb1));
        T[2 * NBINS + t] = make_float4(LUTQ(yb0, xa0), LUTQ(yb0, xa1), LUTQ(yb1, xa0), LUTQ(yb1, xa1));
        T[3 * NBINS + t] = make_float4(LUTQ(yb0, xb0), LUTQ(yb0, xb1), LUTQ(yb1, xb0), LUTQ(yb1, xb1));
        #undef LUTQ
    }
    __syncthreads();

    // apply from retained bins (no input re-read)
    const int qx = j >> 5;
    const float fx = (qx ? ((float)j - 31.5f) : ((float)j + 32.5f)) * (1.0f / TILE);

    const float4* Ta = T + qx * NBINS;          // rows i < 32 (qy=0)
    const float4* Tb = T + (2 + qx) * NBINS;    // rows i >= 32 (qy=1)

    float* q = q0;
    float fy = ((float)i0 + 32.5f) * (1.0f / TILE);   // exact dyadic
    #pragma unroll
    for (int k = 0; k < 8; k++) {
        int bin = (packed[k >> 2] >> ((k & 3) * 8)) & 255;
        float4 tt = Ta[bin];
        float top = fmaf(fx, tt.y - tt.x, tt.x);
        float bot = fmaf(fx, tt.w - tt.z, tt.z);
        __stcs(q, fmaf(fy, bot - top, top));
        q += qstep; fy += (4.0f / TILE);
    }
    fy = ((float)i0 + 0.5f) * (1.0f / TILE);
    #pragma unroll
    for (int k = 8; k < 16; k++) {
        int bin = (packed[k >> 2] >> ((k & 3) * 8)) & 255;
        float4 tt = Tb[bin];
        float top = fmaf(fx, tt.y - tt.x, tt.x);
        float bot = fmaf(fx, tt.w - tt.z, tt.z);
        __stcs(q, fmaf(fy, bot - top, top));
        q += qstep; fy += (4.0f / TILE);
    }
}

extern "C" void kernel_launch(void* const* d_in, const int* in_sizes, int n_in,
                              void* d_out, int out_size) {
    const float* x          = (const float*)d_in[0];
    const int*   hflip      = (const int*)d_in[1];
    const int*   vflip      = (const int*)d_in[2];
    const int*   offy       = (const int*)d_in[3];
    const int*   offx       = (const int*)d_in[4];
    const int*   apply_clahe= (const int*)d_in[5];
    float*       out        = (float*)d_out;

    clahe_fused_kernel<<<NB * GRID_N * GRID_N, NBINS>>>(
        x, hflip, vflip, offy, offx, apply_clahe, out);
}